// round 5
// baseline (speedup 1.0000x reference)
#include <cuda_runtime.h>
#include <math.h>

// ---------------- static scratch (no allocation allowed) ----------------
__device__ float g_enc1[8*256*256*16];   // after trio1
__device__ float g_enc2[8*128*128*16];   // after trio2
__device__ float g_enc3[8*64*64*32];     // after trio3
__device__ float g_dec0[8*256*256*64];   // decoder ping
__device__ float g_dec1[8*256*256*64];   // decoder pong
__device__ float g_m0[8*256*256];        // masks ping
__device__ float g_m1[8*256*256];        // masks pong
__device__ float g_loss;

__device__ __forceinline__ float gelu_f(float x) {
    float x3 = x * x * x;
    return 0.5f * x * (1.0f + tanhf(0.7978845608028654f * (x + 0.044715f * x3)));
}

// ---------------- encoder layer 1: 1->16, stride 1, LN, gelu ----------------
__global__ void conv1_trio(const float* __restrict__ img, const float* __restrict__ w,
                           const float* __restrict__ bias, float* __restrict__ out) {
    __shared__ float ws[144];
    __shared__ float bs[16];
    int tid = threadIdx.x;
    if (tid < 144) ws[tid] = w[tid];
    if (tid < 16)  bs[tid] = bias[tid];
    __syncthreads();
    int p = blockIdx.x * 256 + tid;           // p in [0, 8*256*256)
    int b = p >> 16; int rem = p & 65535;
    int y = rem >> 8; int x = rem & 255;
    float v[16];
#pragma unroll
    for (int i = 0; i < 16; i++) v[i] = bs[i];
    const float* ib = img + (long)b * 65536;
#pragma unroll
    for (int ky = 0; ky < 3; ky++) {
        int iy = y + ky - 1; if ((unsigned)iy >= 256u) continue;
#pragma unroll
        for (int kx = 0; kx < 3; kx++) {
            int ix = x + kx - 1; if ((unsigned)ix >= 256u) continue;
            float xv = ib[iy * 256 + ix];
            const float* wr = &ws[(ky * 3 + kx) * 16];
#pragma unroll
            for (int c = 0; c < 16; c++) v[c] = fmaf(xv, wr[c], v[c]);
        }
    }
    float mu = 0.f;
#pragma unroll
    for (int c = 0; c < 16; c++) mu += v[c];
    mu *= (1.0f / 16.0f);
    float var = 0.f;
#pragma unroll
    for (int c = 0; c < 16; c++) { float d = v[c] - mu; var = fmaf(d, d, var); }
    var *= (1.0f / 16.0f);
    float r = rsqrtf(var + 1e-6f);
    float* o = out + (long)p * 16;
#pragma unroll
    for (int c = 0; c < 16; c++) o[c] = gelu_f((v[c] - mu) * r);
}

// ------------- generic stride-2 conv trio (SAME pad: lo=0, hi=1) -------------
template<int CI, int CO, int HIN, int CHUNK>
__global__ void conv_s2_trio(const float* __restrict__ X, const float* __restrict__ W,
                             const float* __restrict__ bias, float* __restrict__ Y) {
    constexpr int HOUT = HIN / 2;
    constexpr int CO4 = CO / 4;
    __shared__ float4 ws[9 * CHUNK * CO4];
    int tid = threadIdx.x;
    int p = blockIdx.x * 256 + tid;
    int b = p / (HOUT * HOUT); int rem = p % (HOUT * HOUT);
    int y = rem / HOUT, x = rem % HOUT;
    float4 acc[CO4];
#pragma unroll
    for (int i = 0; i < CO4; i++) acc[i] = make_float4(0.f, 0.f, 0.f, 0.f);
    const float4* W4 = (const float4*)W;
    for (int c0 = 0; c0 < CI; c0 += CHUNK) {
        __syncthreads();
        for (int t = tid; t < 9 * CHUNK * CO4; t += 256) {
            int co4 = t % CO4; int ci = (t / CO4) % CHUNK; int tap = t / (CO4 * CHUNK);
            ws[t] = W4[((long)tap * CI + c0 + ci) * CO4 + co4];
        }
        __syncthreads();
        for (int ky = 0; ky < 3; ky++) {
            int iy = 2 * y + ky; if (iy >= HIN) continue;
            for (int kx = 0; kx < 3; kx++) {
                int ix = 2 * x + kx; if (ix >= HIN) continue;
                const float4* xp = (const float4*)(X + ((((long)b * HIN + iy) * HIN + ix) * CI + c0));
                const float4* wt = &ws[(ky * 3 + kx) * CHUNK * CO4];
#pragma unroll
                for (int q = 0; q < CHUNK / 4; q++) {
                    float4 xv = xp[q];
#pragma unroll
                    for (int l = 0; l < 4; l++) {
                        float xs = (l == 0) ? xv.x : (l == 1) ? xv.y : (l == 2) ? xv.z : xv.w;
                        const float4* wr = wt + (q * 4 + l) * CO4;
#pragma unroll
                        for (int co = 0; co < CO4; co++) {
                            acc[co].x = fmaf(xs, wr[co].x, acc[co].x);
                            acc[co].y = fmaf(xs, wr[co].y, acc[co].y);
                            acc[co].z = fmaf(xs, wr[co].z, acc[co].z);
                            acc[co].w = fmaf(xs, wr[co].w, acc[co].w);
                        }
                    }
                }
            }
        }
    }
    // bias + channel LN + gelu
    float mu = 0.f;
#pragma unroll
    for (int i = 0; i < CO4; i++) {
        float4 bb = __ldg(((const float4*)bias) + i);
        acc[i].x += bb.x; acc[i].y += bb.y; acc[i].z += bb.z; acc[i].w += bb.w;
        mu += acc[i].x + acc[i].y + acc[i].z + acc[i].w;
    }
    mu *= (1.0f / CO);
    float var = 0.f;
#pragma unroll
    for (int i = 0; i < CO4; i++) {
        float dx = acc[i].x - mu, dy = acc[i].y - mu, dz = acc[i].z - mu, dw = acc[i].w - mu;
        var += dx * dx + dy * dy + dz * dz + dw * dw;
    }
    var *= (1.0f / CO);
    float r = rsqrtf(var + 1e-6f);
    float4* o = (float4*)(Y + (long)p * CO);
#pragma unroll
    for (int i = 0; i < CO4; i++) {
        o[i] = make_float4(gelu_f((acc[i].x - mu) * r), gelu_f((acc[i].y - mu) * r),
                           gelu_f((acc[i].z - mu) * r), gelu_f((acc[i].w - mu) * r));
    }
}

// ------------- decoder: conv_transpose 64->64, stride (2,1) or (1,2), + gelu -------------
// JAX conv_transpose(SAME,k=3,s=2): unflipped kernel, lhs dilation, pads (2,1):
//   even out idx o: taps ky={0,2} at rows {o/2-1, o/2};  odd o: tap ky=1 at row (o-1)/2.
// stride-1 dim: standard SAME correlation, pad (1,1).
__global__ void deconv_gelu(const float* __restrict__ X, float* __restrict__ Y,
                            const float* __restrict__ W, const float* __restrict__ bias,
                            int h_in, int w_in, int dim) {
    __shared__ float4 ws[2304];   // [tap(9)][ci(16)][co4(16)]
    int tid = threadIdx.x;
    int h_out = (dim == 0) ? (h_in << 1) : h_in;
    int w_out = (dim == 0) ? w_in : (w_in << 1);
    int hw = h_out * w_out;
    int p = blockIdx.x * 256 + tid;
    int b = p / hw; int rem = p % hw;
    int oy = rem / w_out; int j = rem % w_out;
    int ox;
    if (dim == 1) { int half = w_out >> 1; ox = (j < half) ? (j << 1) : (((j - half) << 1) | 1); }
    else ox = j;

    int iy[3], ty[3], ni = 0;
    int ix[3], tx[3], nj = 0;
    if (dim == 0) {
        if ((oy & 1) == 0) {
            int r = (oy >> 1) - 1; if (r >= 0) { iy[ni] = r; ty[ni] = 0; ni++; }
            r = oy >> 1;           if (r < h_in) { iy[ni] = r; ty[ni] = 2; ni++; }
        } else { iy[0] = oy >> 1; ty[0] = 1; ni = 1; }
        for (int k = 0; k < 3; k++) { int c = ox + k - 1; if (c >= 0 && c < w_in) { ix[nj] = c; tx[nj] = k; nj++; } }
    } else {
        for (int k = 0; k < 3; k++) { int r = oy + k - 1; if (r >= 0 && r < h_in) { iy[ni] = r; ty[ni] = k; ni++; } }
        if ((ox & 1) == 0) {
            int c = (ox >> 1) - 1; if (c >= 0) { ix[nj] = c; tx[nj] = 0; nj++; }
            c = ox >> 1;           if (c < w_in) { ix[nj] = c; tx[nj] = 2; nj++; }
        } else { ix[0] = ox >> 1; tx[0] = 1; nj = 1; }
    }

    float4 acc[16];
#pragma unroll
    for (int i = 0; i < 16; i++) acc[i] = make_float4(0.f, 0.f, 0.f, 0.f);
    const float4* W4 = (const float4*)W;

    for (int c0 = 0; c0 < 64; c0 += 16) {
        __syncthreads();
        for (int t = tid; t < 2304; t += 256) {
            int co4 = t & 15; int ci = (t >> 4) & 15; int tap = t >> 8;
            ws[t] = W4[((long)tap * 64 + c0 + ci) * 16 + co4];
        }
        __syncthreads();
        for (int a = 0; a < ni; a++) {
            for (int e = 0; e < nj; e++) {
                int tap = ty[a] * 3 + tx[e];
                const float4* xp = (const float4*)(X + ((((long)b * h_in + iy[a]) * w_in + ix[e]) << 6) + c0);
                const float4* wt = &ws[tap << 8];
#pragma unroll
                for (int q = 0; q < 4; q++) {
                    float4 xv = xp[q];
#pragma unroll
                    for (int l = 0; l < 4; l++) {
                        float xs = (l == 0) ? xv.x : (l == 1) ? xv.y : (l == 2) ? xv.z : xv.w;
                        const float4* wr = wt + ((q * 4 + l) << 4);
#pragma unroll
                        for (int co = 0; co < 16; co++) {
                            acc[co].x = fmaf(xs, wr[co].x, acc[co].x);
                            acc[co].y = fmaf(xs, wr[co].y, acc[co].y);
                            acc[co].z = fmaf(xs, wr[co].z, acc[co].z);
                            acc[co].w = fmaf(xs, wr[co].w, acc[co].w);
                        }
                    }
                }
            }
        }
    }
    float4* o = (float4*)(Y + ((((long)b * h_out + oy) * w_out + ox) << 6));
#pragma unroll
    for (int co = 0; co < 16; co++) {
        float4 bb = __ldg(((const float4*)bias) + co);
        o[co] = make_float4(gelu_f(acc[co].x + bb.x), gelu_f(acc[co].y + bb.y),
                            gelu_f(acc[co].z + bb.z), gelu_f(acc[co].w + bb.w));
    }
}

// ------- mask conv(64->4) + softmax + entropy + img pool + masks update + loss -------
__global__ void mask_loss(const float* __restrict__ D, const float* __restrict__ mw,
                          const float* __restrict__ mb, const float* __restrict__ img,
                          const float* __restrict__ masks_in, float* __restrict__ masks_out,
                          int h, int w, int dim, float scale, float* __restrict__ loss) {
    __shared__ float4 ws[576];   // [tap(9)][ci(64)] -> float4 over 4 out channels
    __shared__ float red[256];
    int tid = threadIdx.x;
    const float4* mw4 = (const float4*)mw;
    for (int t = tid; t < 576; t += 256) ws[t] = mw4[t];
    __syncthreads();
    int p = blockIdx.x * 256 + tid;
    int hw = h * w;
    int b = p / hw; int rem = p % hw; int oy = rem / w; int ox = rem % w;
    float4 lg = make_float4(__ldg(mb + 0), __ldg(mb + 1), __ldg(mb + 2), __ldg(mb + 3));
    for (int ky = 0; ky < 3; ky++) {
        int iy = oy + ky - 1; if ((unsigned)iy >= (unsigned)h) continue;
        for (int kx = 0; kx < 3; kx++) {
            int ix = ox + kx - 1; if ((unsigned)ix >= (unsigned)w) continue;
            const float4* xp = (const float4*)(D + ((((long)b * h + iy) * w + ix) << 6));
            const float4* wt = &ws[(ky * 3 + kx) * 64];
#pragma unroll
            for (int q = 0; q < 16; q++) {
                float4 xv = xp[q];
                const float4* wr = wt + q * 4;
                lg.x = fmaf(xv.x, wr[0].x, lg.x); lg.y = fmaf(xv.x, wr[0].y, lg.y);
                lg.z = fmaf(xv.x, wr[0].z, lg.z); lg.w = fmaf(xv.x, wr[0].w, lg.w);
                lg.x = fmaf(xv.y, wr[1].x, lg.x); lg.y = fmaf(xv.y, wr[1].y, lg.y);
                lg.z = fmaf(xv.y, wr[1].z, lg.z); lg.w = fmaf(xv.y, wr[1].w, lg.w);
                lg.x = fmaf(xv.z, wr[2].x, lg.x); lg.y = fmaf(xv.z, wr[2].y, lg.y);
                lg.z = fmaf(xv.z, wr[2].z, lg.z); lg.w = fmaf(xv.z, wr[2].w, lg.w);
                lg.x = fmaf(xv.w, wr[3].x, lg.x); lg.y = fmaf(xv.w, wr[3].y, lg.y);
                lg.z = fmaf(xv.w, wr[3].z, lg.z); lg.w = fmaf(xv.w, wr[3].w, lg.w);
            }
        }
    }
    // softmax over 4
    float m = fmaxf(fmaxf(lg.x, lg.y), fmaxf(lg.z, lg.w));
    float e0 = expf(lg.x - m), e1 = expf(lg.y - m), e2 = expf(lg.z - m), e3 = expf(lg.w - m);
    float inv = 1.0f / (e0 + e1 + e2 + e3);
    float p0 = e0 * inv, p1 = e1 * inv, p2 = e2 * inv, p3 = e3 * inv;
    float sel = p1 + 2.0f * p2 + 3.0f * p3;
    float ent = -(p0 * logf(p0 + 1e-8f) + p1 * logf(p1 + 1e-8f)
                + p2 * logf(p2 + 1e-8f) + p3 * logf(p3 + 1e-8f));
    // average-pooled image at (oy, ox)
    int ph = 256 / h, pw = 256 / w;
    const float* ip = img + (((long)b * 256 + (long)oy * ph) * 256 + (long)ox * pw);
    float s = 0.f;
    for (int a = 0; a < ph; a++)
        for (int c = 0; c < pw; c++) s += ip[a * 256 + c];
    float ids = s / (float)(ph * pw);
    float d = sel * (1.0f / 3.0f) - ids;
    // masks update (repeat along dim, then += 0.25*sel)
    long src;
    if (dim == 0) src = ((long)b * (h >> 1) + (oy >> 1)) * w + ox;
    else          src = ((long)b * h + oy) * (w >> 1) + (ox >> 1);
    masks_out[p] = masks_in[src] + 0.25f * sel;
    // loss reduction: LOSS_W * (mean(entropy) + mean(sqerr))
    red[tid] = ent + d * d;
    __syncthreads();
    for (int off = 128; off > 0; off >>= 1) {
        if (tid < off) red[tid] += red[tid + off];
        __syncthreads();
    }
    if (tid == 0) atomicAdd(loss, red[0] * scale);
}

__global__ void zero_loss_k() { g_loss = 0.0f; }
__global__ void finalize_k(float* out) { out[0] = g_loss; }

// ---------------------------------------------------------------------------
extern "C" void kernel_launch(void* const* d_in, const int* in_sizes, int n_in,
                              void* d_out, int out_size) {
    const float* image  = (const float*)d_in[0];
    // d_in[1] = dynamic_cfg (unused)
    const float* w1 = (const float*)d_in[2];  const float* b1 = (const float*)d_in[3];
    const float* w2 = (const float*)d_in[4];  const float* b2 = (const float*)d_in[5];
    const float* w3 = (const float*)d_in[6];  const float* b3 = (const float*)d_in[7];
    const float* w4 = (const float*)d_in[8];  const float* b4 = (const float*)d_in[9];
    const float* up_w = (const float*)d_in[10]; const float* up_b = (const float*)d_in[11];
    const float* mask_w = (const float*)d_in[12]; const float* mask_b = (const float*)d_in[13];
    const float* masks0 = (const float*)d_in[14];
    float* out = (float*)d_out;

    float *e1, *e2, *e3, *dc0, *dc1, *m0, *m1, *lossp;
    cudaGetSymbolAddress((void**)&e1,  g_enc1);
    cudaGetSymbolAddress((void**)&e2,  g_enc2);
    cudaGetSymbolAddress((void**)&e3,  g_enc3);
    cudaGetSymbolAddress((void**)&dc0, g_dec0);
    cudaGetSymbolAddress((void**)&dc1, g_dec1);
    cudaGetSymbolAddress((void**)&m0,  g_m0);
    cudaGetSymbolAddress((void**)&m1,  g_m1);
    cudaGetSymbolAddress((void**)&lossp, g_loss);

    zero_loss_k<<<1, 1>>>();

    conv1_trio<<<(8 * 256 * 256) / 256, 256>>>(image, w1, b1, e1);
    conv_s2_trio<16, 16, 256, 16><<<(8 * 128 * 128) / 256, 256>>>(e1, w2, b2, e2);
    conv_s2_trio<16, 32, 128, 16><<<(8 * 64 * 64) / 256, 256>>>(e2, w3, b3, e3);
    conv_s2_trio<32, 64, 64, 16><<<(8 * 32 * 32) / 256, 256>>>(e3, w4, b4, dc0);

    const float lws[6] = {0.1f, 0.1f, 0.5f, 0.5f, 1.0f, 1.0f};
    const float* din = dc0;  float* dout_ = dc1;
    const float* min_ = masks0;
    float* mbuf[2] = {m0, m1};
    int h = 32, w = 32;
    for (int i = 0; i < 6; i++) {
        int dim = i % 2;
        int ho = (dim == 0) ? 2 * h : h;
        int wo = (dim == 0) ? w : 2 * w;
        int px = 8 * ho * wo;
        deconv_gelu<<<px / 256, 256>>>(din, dout_, up_w, up_b, h, w, dim);
        float* mout = (i == 5) ? (out + 1) : mbuf[i % 2];
        float scale = lws[i] / (float)px;
        mask_loss<<<px / 256, 256>>>(dout_, mask_w, mask_b, image, min_, mout,
                                     ho, wo, dim, scale, lossp);
        min_ = mout;
        const float* t = din; din = dout_; dout_ = (float*)t;
        h = ho; w = wo;
    }
    finalize_k<<<1, 1>>>(out);
}

// round 10
// speedup vs baseline: 1.6072x; 1.6072x over previous
#include <cuda_runtime.h>
#include <math.h>

// ---------------- static scratch (no allocation allowed) ----------------
__device__ float g_enc1[8*256*256*16];   // after trio1
__device__ float g_enc2[8*128*128*16];   // after trio2
__device__ float g_enc3[8*64*64*32];     // after trio3
__device__ float g_dec0[8*256*256*64];   // decoder ping
__device__ float g_dec1[8*256*256*64];   // decoder pong
__device__ float g_m0[8*256*256];        // masks ping
__device__ float g_m1[8*256*256];        // masks pong
__device__ float g_loss;

__device__ __forceinline__ float gelu_f(float x) {
    float x3 = x * x * x;
    return 0.5f * x * (1.0f + tanhf(0.7978845608028654f * (x + 0.044715f * x3)));
}

// ---------------- encoder layer 1: 1->16, stride 1, LN, gelu ----------------
__global__ void conv1_trio(const float* __restrict__ img, const float* __restrict__ w,
                           const float* __restrict__ bias, float* __restrict__ out) {
    __shared__ float ws[144];
    __shared__ float bs[16];
    int tid = threadIdx.x;
    if (tid < 144) ws[tid] = w[tid];
    if (tid < 16)  bs[tid] = bias[tid];
    __syncthreads();
    int p = blockIdx.x * 256 + tid;           // p in [0, 8*256*256)
    int b = p >> 16; int rem = p & 65535;
    int y = rem >> 8; int x = rem & 255;
    float v[16];
#pragma unroll
    for (int i = 0; i < 16; i++) v[i] = bs[i];
    const float* ib = img + (long)b * 65536;
#pragma unroll
    for (int ky = 0; ky < 3; ky++) {
        int iy = y + ky - 1; if ((unsigned)iy >= 256u) continue;
#pragma unroll
        for (int kx = 0; kx < 3; kx++) {
            int ix = x + kx - 1; if ((unsigned)ix >= 256u) continue;
            float xv = ib[iy * 256 + ix];
            const float* wr = &ws[(ky * 3 + kx) * 16];
#pragma unroll
            for (int c = 0; c < 16; c++) v[c] = fmaf(xv, wr[c], v[c]);
        }
    }
    float mu = 0.f;
#pragma unroll
    for (int c = 0; c < 16; c++) mu += v[c];
    mu *= (1.0f / 16.0f);
    float var = 0.f;
#pragma unroll
    for (int c = 0; c < 16; c++) { float d = v[c] - mu; var = fmaf(d, d, var); }
    var *= (1.0f / 16.0f);
    float r = rsqrtf(var + 1e-6f);
    float* o = out + (long)p * 16;
#pragma unroll
    for (int c = 0; c < 16; c++) o[c] = gelu_f((v[c] - mu) * r);
}

// ------------- generic stride-2 conv trio (SAME pad: lo=0, hi=1) -------------
template<int CI, int CO, int HIN, int CHUNK>
__global__ void conv_s2_trio(const float* __restrict__ X, const float* __restrict__ W,
                             const float* __restrict__ bias, float* __restrict__ Y) {
    constexpr int HOUT = HIN / 2;
    constexpr int CO4 = CO / 4;
    __shared__ float4 ws[9 * CHUNK * CO4];
    int tid = threadIdx.x;
    int p = blockIdx.x * 256 + tid;
    int b = p / (HOUT * HOUT); int rem = p % (HOUT * HOUT);
    int y = rem / HOUT, x = rem % HOUT;
    float4 acc[CO4];
#pragma unroll
    for (int i = 0; i < CO4; i++) acc[i] = make_float4(0.f, 0.f, 0.f, 0.f);
    const float4* W4 = (const float4*)W;
    for (int c0 = 0; c0 < CI; c0 += CHUNK) {
        __syncthreads();
        for (int t = tid; t < 9 * CHUNK * CO4; t += 256) {
            int co4 = t % CO4; int ci = (t / CO4) % CHUNK; int tap = t / (CO4 * CHUNK);
            ws[t] = W4[((long)tap * CI + c0 + ci) * CO4 + co4];
        }
        __syncthreads();
        for (int ky = 0; ky < 3; ky++) {
            int iy = 2 * y + ky; if (iy >= HIN) continue;
            for (int kx = 0; kx < 3; kx++) {
                int ix = 2 * x + kx; if (ix >= HIN) continue;
                const float4* xp = (const float4*)(X + ((((long)b * HIN + iy) * HIN + ix) * CI + c0));
                const float4* wt = &ws[(ky * 3 + kx) * CHUNK * CO4];
#pragma unroll
                for (int q = 0; q < CHUNK / 4; q++) {
                    float4 xv = xp[q];
#pragma unroll
                    for (int l = 0; l < 4; l++) {
                        float xs = (l == 0) ? xv.x : (l == 1) ? xv.y : (l == 2) ? xv.z : xv.w;
                        const float4* wr = wt + (q * 4 + l) * CO4;
#pragma unroll
                        for (int co = 0; co < CO4; co++) {
                            acc[co].x = fmaf(xs, wr[co].x, acc[co].x);
                            acc[co].y = fmaf(xs, wr[co].y, acc[co].y);
                            acc[co].z = fmaf(xs, wr[co].z, acc[co].z);
                            acc[co].w = fmaf(xs, wr[co].w, acc[co].w);
                        }
                    }
                }
            }
        }
    }
    // bias + channel LN + gelu
    float mu = 0.f;
#pragma unroll
    for (int i = 0; i < CO4; i++) {
        float4 bb = __ldg(((const float4*)bias) + i);
        acc[i].x += bb.x; acc[i].y += bb.y; acc[i].z += bb.z; acc[i].w += bb.w;
        mu += acc[i].x + acc[i].y + acc[i].z + acc[i].w;
    }
    mu *= (1.0f / CO);
    float var = 0.f;
#pragma unroll
    for (int i = 0; i < CO4; i++) {
        float dx = acc[i].x - mu, dy = acc[i].y - mu, dz = acc[i].z - mu, dw = acc[i].w - mu;
        var += dx * dx + dy * dy + dz * dz + dw * dw;
    }
    var *= (1.0f / CO);
    float r = rsqrtf(var + 1e-6f);
    float4* o = (float4*)(Y + (long)p * CO);
#pragma unroll
    for (int i = 0; i < CO4; i++) {
        o[i] = make_float4(gelu_f((acc[i].x - mu) * r), gelu_f((acc[i].y - mu) * r),
                           gelu_f((acc[i].z - mu) * r), gelu_f((acc[i].w - mu) * r));
    }
}

// ------------- decoder conv_transpose 64->64 as parity-split implicit GEMM -------------
// JAX conv_transpose(SAME,k=3,s=2): unflipped kernel, lhs dilation, pads (2,1):
//   even out idx o: taps k={0,2} at in rows {o/2-1, o/2};  odd o: tap k=1 at row (o-1)/2.
// Each parity class has exactly B*h_in*w_in pixels and a FIXED tap list (6 or 3 taps).
// Block: 128 px x 64 co.  Thread: 8 px x 4 co (32 fp32 accumulators).
__global__ __launch_bounds__(256) void deconv_gemm(
        const float* __restrict__ X, float* __restrict__ Y,
        const float* __restrict__ W, const float* __restrict__ bias,
        int h_in, int w_in, int hw_sh, int w_sh, int dim, int parity, int ntap) {
    __shared__ float  Xs[64 * 128];   // [ci][px]  32KB
    __shared__ float4 Ws[64 * 16];    // [ci][co4] 16KB (one tap at a time)
    int tid = threadIdx.x;

    // tap tables: (dy, dx) source offset from class coords, wt = ky*3+kx weight tap
    int dy[6], dx[6], wt[6];
    if (dim == 0) {
        if (parity == 0) {
#pragma unroll
            for (int kx = 0; kx < 3; kx++) { dy[kx] = -1; dx[kx] = kx - 1; wt[kx] = kx;
                                             dy[3+kx] = 0; dx[3+kx] = kx - 1; wt[3+kx] = 6 + kx; }
        } else {
#pragma unroll
            for (int kx = 0; kx < 3; kx++) { dy[kx] = 0; dx[kx] = kx - 1; wt[kx] = 3 + kx; }
        }
    } else {
        if (parity == 0) {
#pragma unroll
            for (int ky = 0; ky < 3; ky++) { dy[ky] = ky - 1; dx[ky] = -1; wt[ky] = 3 * ky;
                                             dy[3+ky] = ky - 1; dx[3+ky] = 0; wt[3+ky] = 3 * ky + 2; }
        } else {
#pragma unroll
            for (int ky = 0; ky < 3; ky++) { dy[ky] = ky - 1; dx[ky] = 0; wt[ky] = 3 * ky + 1; }
        }
    }

    int q0 = blockIdx.x * 128;
    // gather-role decode: this thread loads px mg, channel half
    int mg = tid >> 1, half = tid & 1;
    int qg = q0 + mg;
    int bg = qg >> hw_sh; int remg = qg & ((1 << hw_sh) - 1);
    int yg = remg >> w_sh; int xg = remg & (w_in - 1);

    float4 acc[8];
#pragma unroll
    for (int i = 0; i < 8; i++) acc[i] = make_float4(0.f, 0.f, 0.f, 0.f);
    int nc = tid & 15, pr = tid >> 4;
    const float4* W4 = (const float4*)W;

    for (int t = 0; t < ntap; t++) {
        __syncthreads();
        // stage weights for this tap: 64ci x 16 co4
        {
            const float4* wsrc = W4 + wt[t] * 1024;
#pragma unroll
            for (int j = 0; j < 4; j++) Ws[tid + j * 256] = wsrc[tid + j * 256];
        }
        // stage X tile transposed [ci][px], zero-filled at boundaries
        {
            int sy = yg + dy[t], sx = xg + dx[t];
            bool valid = (sy >= 0) && (sy < h_in) && (sx >= 0) && (sx < w_in);
            const float4* src = (const float4*)(X +
                ((((long)bg << hw_sh) + ((long)sy << w_sh) + sx) << 6)) + half * 8;
#pragma unroll
            for (int j = 0; j < 8; j++) {
                float4 v = valid ? src[j] : make_float4(0.f, 0.f, 0.f, 0.f);
                int k = half * 32 + j * 4;
                Xs[(k + 0) * 128 + mg] = v.x;
                Xs[(k + 1) * 128 + mg] = v.y;
                Xs[(k + 2) * 128 + mg] = v.z;
                Xs[(k + 3) * 128 + mg] = v.w;
            }
        }
        __syncthreads();
        // accumulate: 64 k-steps, 32 FFMA per step per thread
#pragma unroll 8
        for (int k = 0; k < 64; k++) {
            float4 wv = Ws[k * 16 + nc];
            const float* xr = &Xs[k * 128 + pr * 8];
            float4 xa = *(const float4*)xr;
            float4 xb = *(const float4*)(xr + 4);
            float xs[8] = {xa.x, xa.y, xa.z, xa.w, xb.x, xb.y, xb.z, xb.w};
#pragma unroll
            for (int i = 0; i < 8; i++) {
                acc[i].x = fmaf(xs[i], wv.x, acc[i].x);
                acc[i].y = fmaf(xs[i], wv.y, acc[i].y);
                acc[i].z = fmaf(xs[i], wv.z, acc[i].z);
                acc[i].w = fmaf(xs[i], wv.w, acc[i].w);
            }
        }
    }
    // epilogue: bias + gelu, scatter to interleaved output positions
    float4 bb = __ldg(((const float4*)bias) + nc);
    int h_out = (dim == 0) ? (h_in << 1) : h_in;
    int w_out = (dim == 0) ? w_in : (w_in << 1);
#pragma unroll
    for (int i = 0; i < 8; i++) {
        int q = q0 + pr * 8 + i;
        int b = q >> hw_sh; int rem = q & ((1 << hw_sh) - 1);
        int y = rem >> w_sh; int x = rem & (w_in - 1);
        int oy = (dim == 0) ? (2 * y + parity) : y;
        int ox = (dim == 0) ? x : (2 * x + parity);
        float4 r;
        r.x = gelu_f(acc[i].x + bb.x);
        r.y = gelu_f(acc[i].y + bb.y);
        r.z = gelu_f(acc[i].z + bb.z);
        r.w = gelu_f(acc[i].w + bb.w);
        *((float4*)(Y + ((((long)b * h_out + oy) * w_out + ox) << 6) + nc * 4)) = r;
    }
}

// ------- mask conv(64->4) + softmax + entropy + img pool + masks update + loss -------
__global__ void mask_loss(const float* __restrict__ D, const float* __restrict__ mw,
                          const float* __restrict__ mb, const float* __restrict__ img,
                          const float* __restrict__ masks_in, float* __restrict__ masks_out,
                          int h, int w, int dim, float scale, float* __restrict__ loss) {
    __shared__ float4 ws[576];   // [tap(9)][ci(64)] -> float4 over 4 out channels
    __shared__ float red[256];
    int tid = threadIdx.x;
    const float4* mw4 = (const float4*)mw;
    for (int t = tid; t < 576; t += 256) ws[t] = mw4[t];
    __syncthreads();
    int p = blockIdx.x * 256 + tid;
    int hw = h * w;
    int b = p / hw; int rem = p % hw; int oy = rem / w; int ox = rem % w;
    float4 lg = make_float4(__ldg(mb + 0), __ldg(mb + 1), __ldg(mb + 2), __ldg(mb + 3));
    for (int ky = 0; ky < 3; ky++) {
        int iy = oy + ky - 1; if ((unsigned)iy >= (unsigned)h) continue;
        for (int kx = 0; kx < 3; kx++) {
            int ix = ox + kx - 1; if ((unsigned)ix >= (unsigned)w) continue;
            const float4* xp = (const float4*)(D + ((((long)b * h + iy) * w + ix) << 6));
            const float4* wt = &ws[(ky * 3 + kx) * 64];
#pragma unroll
            for (int q = 0; q < 16; q++) {
                float4 xv = xp[q];
                const float4* wr = wt + q * 4;
                lg.x = fmaf(xv.x, wr[0].x, lg.x); lg.y = fmaf(xv.x, wr[0].y, lg.y);
                lg.z = fmaf(xv.x, wr[0].z, lg.z); lg.w = fmaf(xv.x, wr[0].w, lg.w);
                lg.x = fmaf(xv.y, wr[1].x, lg.x); lg.y = fmaf(xv.y, wr[1].y, lg.y);
                lg.z = fmaf(xv.y, wr[1].z, lg.z); lg.w = fmaf(xv.y, wr[1].w, lg.w);
                lg.x = fmaf(xv.z, wr[2].x, lg.x); lg.y = fmaf(xv.z, wr[2].y, lg.y);
                lg.z = fmaf(xv.z, wr[2].z, lg.z); lg.w = fmaf(xv.z, wr[2].w, lg.w);
                lg.x = fmaf(xv.w, wr[3].x, lg.x); lg.y = fmaf(xv.w, wr[3].y, lg.y);
                lg.z = fmaf(xv.w, wr[3].z, lg.z); lg.w = fmaf(xv.w, wr[3].w, lg.w);
            }
        }
    }
    // softmax over 4
    float m = fmaxf(fmaxf(lg.x, lg.y), fmaxf(lg.z, lg.w));
    float e0 = expf(lg.x - m), e1 = expf(lg.y - m), e2 = expf(lg.z - m), e3 = expf(lg.w - m);
    float inv = 1.0f / (e0 + e1 + e2 + e3);
    float p0 = e0 * inv, p1 = e1 * inv, p2 = e2 * inv, p3 = e3 * inv;
    float sel = p1 + 2.0f * p2 + 3.0f * p3;
    float ent = -(p0 * logf(p0 + 1e-8f) + p1 * logf(p1 + 1e-8f)
                + p2 * logf(p2 + 1e-8f) + p3 * logf(p3 + 1e-8f));
    // average-pooled image at (oy, ox)
    int ph = 256 / h, pw = 256 / w;
    const float* ip = img + (((long)b * 256 + (long)oy * ph) * 256 + (long)ox * pw);
    float s = 0.f;
    for (int a = 0; a < ph; a++)
        for (int c = 0; c < pw; c++) s += ip[a * 256 + c];
    float ids = s / (float)(ph * pw);
    float d = sel * (1.0f / 3.0f) - ids;
    // masks update (repeat along dim, then += 0.25*sel)
    long src;
    if (dim == 0) src = ((long)b * (h >> 1) + (oy >> 1)) * w + ox;
    else          src = ((long)b * h + oy) * (w >> 1) + (ox >> 1);
    masks_out[p] = masks_in[src] + 0.25f * sel;
    // loss reduction: LOSS_W * (mean(entropy) + mean(sqerr))
    red[tid] = ent + d * d;
    __syncthreads();
    for (int off = 128; off > 0; off >>= 1) {
        if (tid < off) red[tid] += red[tid + off];
        __syncthreads();
    }
    if (tid == 0) atomicAdd(loss, red[0] * scale);
}

__global__ void zero_loss_k() { g_loss = 0.0f; }
__global__ void finalize_k(float* out) { out[0] = g_loss; }

static inline int ilog2i(int v) { int s = 0; while ((1 << s) < v) s++; return s; }

// ---------------------------------------------------------------------------
extern "C" void kernel_launch(void* const* d_in, const int* in_sizes, int n_in,
                              void* d_out, int out_size) {
    const float* image  = (const float*)d_in[0];
    // d_in[1] = dynamic_cfg (unused)
    const float* w1 = (const float*)d_in[2];  const float* b1 = (const float*)d_in[3];
    const float* w2 = (const float*)d_in[4];  const float* b2 = (const float*)d_in[5];
    const float* w3 = (const float*)d_in[6];  const float* b3 = (const float*)d_in[7];
    const float* w4 = (const float*)d_in[8];  const float* b4 = (const float*)d_in[9];
    const float* up_w = (const float*)d_in[10]; const float* up_b = (const float*)d_in[11];
    const float* mask_w = (const float*)d_in[12]; const float* mask_b = (const float*)d_in[13];
    const float* masks0 = (const float*)d_in[14];
    float* out = (float*)d_out;

    float *e1, *e2, *e3, *dc0, *dc1, *m0, *m1, *lossp;
    cudaGetSymbolAddress((void**)&e1,  g_enc1);
    cudaGetSymbolAddress((void**)&e2,  g_enc2);
    cudaGetSymbolAddress((void**)&e3,  g_enc3);
    cudaGetSymbolAddress((void**)&dc0, g_dec0);
    cudaGetSymbolAddress((void**)&dc1, g_dec1);
    cudaGetSymbolAddress((void**)&m0,  g_m0);
    cudaGetSymbolAddress((void**)&m1,  g_m1);
    cudaGetSymbolAddress((void**)&lossp, g_loss);

    zero_loss_k<<<1, 1>>>();

    conv1_trio<<<(8 * 256 * 256) / 256, 256>>>(image, w1, b1, e1);
    conv_s2_trio<16, 16, 256, 16><<<(8 * 128 * 128) / 256, 256>>>(e1, w2, b2, e2);
    conv_s2_trio<16, 32, 128, 16><<<(8 * 64 * 64) / 256, 256>>>(e2, w3, b3, e3);
    conv_s2_trio<32, 64, 64, 16><<<(8 * 32 * 32) / 256, 256>>>(e3, w4, b4, dc0);

    const float lws[6] = {0.1f, 0.1f, 0.5f, 0.5f, 1.0f, 1.0f};
    const float* din = dc0;  float* dout_ = dc1;
    const float* min_ = masks0;
    float* mbuf[2] = {m0, m1};
    int h = 32, w = 32;
    for (int i = 0; i < 6; i++) {
        int dim = i % 2;
        int ho = (dim == 0) ? 2 * h : h;
        int wo = (dim == 0) ? w : 2 * w;
        int px = 8 * ho * wo;
        int cls_px = 8 * h * w;                 // pixels per parity class
        int blocks = cls_px / 128;
        int hw_sh = ilog2i(h * w), w_sh = ilog2i(w);
        deconv_gemm<<<blocks, 256>>>(din, dout_, up_w, up_b, h, w, hw_sh, w_sh, dim, 0, 6);
        deconv_gemm<<<blocks, 256>>>(din, dout_, up_w, up_b, h, w, hw_sh, w_sh, dim, 1, 3);
        float* mout = (i == 5) ? (out + 1) : mbuf[i % 2];
        float scale = lws[i] / (float)px;
        mask_loss<<<px / 256, 256>>>(dout_, mask_w, mask_b, image, min_, mout,
                                     ho, wo, dim, scale, lossp);
        min_ = mout;
        const float* t = din; din = dout_; dout_ = (float*)t;
        h = ho; w = wo;
    }
    finalize_k<<<1, 1>>>(out);
}

// round 12
// speedup vs baseline: 1.6143x; 1.0045x over previous
#include <cuda_runtime.h>
#include <math.h>
#include <stdint.h>

// ---------------- static scratch (no allocation allowed) ----------------
__device__ float g_enc1[8*256*256*16];   // after trio1
__device__ float g_enc2[8*128*128*16];   // after trio2
__device__ float g_enc3[8*64*64*32];     // after trio3
__device__ float g_dec0[8*256*256*64];   // decoder ping
__device__ float g_dec1[8*256*256*64];   // decoder pong
__device__ float g_m0[8*256*256];        // masks ping
__device__ float g_m1[8*256*256];        // masks pong
__device__ float g_loss;

__device__ __forceinline__ float gelu_f(float x) {
    float x3 = x * x * x;
    return 0.5f * x * (1.0f + tanhf(0.7978845608028654f * (x + 0.044715f * x3)));
}

// ---------------- encoder layer 1: 1->16, stride 1, LN, gelu ----------------
__global__ void conv1_trio(const float* __restrict__ img, const float* __restrict__ w,
                           const float* __restrict__ bias, float* __restrict__ out) {
    __shared__ float ws[144];
    __shared__ float bs[16];
    int tid = threadIdx.x;
    if (tid < 144) ws[tid] = w[tid];
    if (tid < 16)  bs[tid] = bias[tid];
    __syncthreads();
    int p = blockIdx.x * 256 + tid;           // p in [0, 8*256*256)
    int b = p >> 16; int rem = p & 65535;
    int y = rem >> 8; int x = rem & 255;
    float v[16];
#pragma unroll
    for (int i = 0; i < 16; i++) v[i] = bs[i];
    const float* ib = img + (long)b * 65536;
#pragma unroll
    for (int ky = 0; ky < 3; ky++) {
        int iy = y + ky - 1; if ((unsigned)iy >= 256u) continue;
#pragma unroll
        for (int kx = 0; kx < 3; kx++) {
            int ix = x + kx - 1; if ((unsigned)ix >= 256u) continue;
            float xv = ib[iy * 256 + ix];
            const float* wr = &ws[(ky * 3 + kx) * 16];
#pragma unroll
            for (int c = 0; c < 16; c++) v[c] = fmaf(xv, wr[c], v[c]);
        }
    }
    float mu = 0.f;
#pragma unroll
    for (int c = 0; c < 16; c++) mu += v[c];
    mu *= (1.0f / 16.0f);
    float var = 0.f;
#pragma unroll
    for (int c = 0; c < 16; c++) { float d = v[c] - mu; var = fmaf(d, d, var); }
    var *= (1.0f / 16.0f);
    float r = rsqrtf(var + 1e-6f);
    float* o = out + (long)p * 16;
#pragma unroll
    for (int c = 0; c < 16; c++) o[c] = gelu_f((v[c] - mu) * r);
}

// ------------- generic stride-2 conv trio (SAME pad: lo=0, hi=1) -------------
template<int CI, int CO, int HIN, int CHUNK>
__global__ void conv_s2_trio(const float* __restrict__ X, const float* __restrict__ W,
                             const float* __restrict__ bias, float* __restrict__ Y) {
    constexpr int HOUT = HIN / 2;
    constexpr int CO4 = CO / 4;
    __shared__ float4 ws[9 * CHUNK * CO4];
    int tid = threadIdx.x;
    int p = blockIdx.x * 256 + tid;
    int b = p / (HOUT * HOUT); int rem = p % (HOUT * HOUT);
    int y = rem / HOUT, x = rem % HOUT;
    float4 acc[CO4];
#pragma unroll
    for (int i = 0; i < CO4; i++) acc[i] = make_float4(0.f, 0.f, 0.f, 0.f);
    const float4* W4 = (const float4*)W;
    for (int c0 = 0; c0 < CI; c0 += CHUNK) {
        __syncthreads();
        for (int t = tid; t < 9 * CHUNK * CO4; t += 256) {
            int co4 = t % CO4; int ci = (t / CO4) % CHUNK; int tap = t / (CO4 * CHUNK);
            ws[t] = W4[((long)tap * CI + c0 + ci) * CO4 + co4];
        }
        __syncthreads();
        for (int ky = 0; ky < 3; ky++) {
            int iy = 2 * y + ky; if (iy >= HIN) continue;
            for (int kx = 0; kx < 3; kx++) {
                int ix = 2 * x + kx; if (ix >= HIN) continue;
                const float4* xp = (const float4*)(X + ((((long)b * HIN + iy) * HIN + ix) * CI + c0));
                const float4* wt = &ws[(ky * 3 + kx) * CHUNK * CO4];
#pragma unroll
                for (int q = 0; q < CHUNK / 4; q++) {
                    float4 xv = xp[q];
#pragma unroll
                    for (int l = 0; l < 4; l++) {
                        float xs = (l == 0) ? xv.x : (l == 1) ? xv.y : (l == 2) ? xv.z : xv.w;
                        const float4* wr = wt + (q * 4 + l) * CO4;
#pragma unroll
                        for (int co = 0; co < CO4; co++) {
                            acc[co].x = fmaf(xs, wr[co].x, acc[co].x);
                            acc[co].y = fmaf(xs, wr[co].y, acc[co].y);
                            acc[co].z = fmaf(xs, wr[co].z, acc[co].z);
                            acc[co].w = fmaf(xs, wr[co].w, acc[co].w);
                        }
                    }
                }
            }
        }
    }
    // bias + channel LN + gelu
    float mu = 0.f;
#pragma unroll
    for (int i = 0; i < CO4; i++) {
        float4 bb = __ldg(((const float4*)bias) + i);
        acc[i].x += bb.x; acc[i].y += bb.y; acc[i].z += bb.z; acc[i].w += bb.w;
        mu += acc[i].x + acc[i].y + acc[i].z + acc[i].w;
    }
    mu *= (1.0f / CO);
    float var = 0.f;
#pragma unroll
    for (int i = 0; i < CO4; i++) {
        float dx = acc[i].x - mu, dy = acc[i].y - mu, dz = acc[i].z - mu, dw = acc[i].w - mu;
        var += dx * dx + dy * dy + dz * dz + dw * dw;
    }
    var *= (1.0f / CO);
    float r = rsqrtf(var + 1e-6f);
    float4* o = (float4*)(Y + (long)p * CO);
#pragma unroll
    for (int i = 0; i < CO4; i++) {
        o[i] = make_float4(gelu_f((acc[i].x - mu) * r), gelu_f((acc[i].y - mu) * r),
                           gelu_f((acc[i].z - mu) * r), gelu_f((acc[i].w - mu) * r));
    }
}

// ------------- decoder conv_transpose 64->64 as parity-split implicit GEMM -------------
// JAX conv_transpose(SAME,k=3,s=2): unflipped kernel, lhs dilation, pads (2,1):
//   even out idx o: taps k={0,2} at in rows {o/2-1, o/2};  odd o: tap k=1 at row (o-1)/2.
// Each parity class has exactly B*h_in*w_in pixels and a FIXED tap list (6 or 3 taps).
// Block: 128 px x 64 co.  Thread: 8 px x 4 co.
// Inner loop uses Blackwell packed fp32 FMA (fma.rn.f32x2): accumulators are
// paired over the PIXEL dim (px pairs are adjacent in Xs[ci][px]), so x-pairs
// load directly as b64; only the 4 w-broadcasts need a pack mov per k-step.
__global__ __launch_bounds__(256) void deconv_gemm(
        const float* __restrict__ X, float* __restrict__ Y,
        const float* __restrict__ W, const float* __restrict__ bias,
        int h_in, int w_in, int hw_sh, int w_sh, int dim, int parity, int ntap) {
    __shared__ float  Xs[64 * 128];   // [ci][px]  32KB
    __shared__ float4 Ws[64 * 16];    // [ci][co4] 16KB (one tap at a time)
    int tid = threadIdx.x;

    // tap tables: (dy, dx) source offset from class coords, wt = ky*3+kx weight tap
    int dy[6], dx[6], wt[6];
    if (dim == 0) {
        if (parity == 0) {
#pragma unroll
            for (int kx = 0; kx < 3; kx++) { dy[kx] = -1; dx[kx] = kx - 1; wt[kx] = kx;
                                             dy[3+kx] = 0; dx[3+kx] = kx - 1; wt[3+kx] = 6 + kx; }
        } else {
#pragma unroll
            for (int kx = 0; kx < 3; kx++) { dy[kx] = 0; dx[kx] = kx - 1; wt[kx] = 3 + kx; }
        }
    } else {
        if (parity == 0) {
#pragma unroll
            for (int ky = 0; ky < 3; ky++) { dy[ky] = ky - 1; dx[ky] = -1; wt[ky] = 3 * ky;
                                             dy[3+ky] = ky - 1; dx[3+ky] = 0; wt[3+ky] = 3 * ky + 2; }
        } else {
#pragma unroll
            for (int ky = 0; ky < 3; ky++) { dy[ky] = ky - 1; dx[ky] = 0; wt[ky] = 3 * ky + 1; }
        }
    }

    int q0 = blockIdx.x * 128;
    // gather-role decode: this thread loads px mg, channel half
    int mg = tid >> 1, half = tid & 1;
    int qg = q0 + mg;
    int bg = qg >> hw_sh; int remg = qg & ((1 << hw_sh) - 1);
    int yg = remg >> w_sh; int xg = remg & (w_in - 1);

    // acc2[cc*4+pp]: packed f32x2 pair = pixels (2pp, 2pp+1) of co channel nc*4+cc
    uint64_t acc2[16];
#pragma unroll
    for (int i = 0; i < 16; i++) acc2[i] = 0ull;     // bit pattern 0 == {0.f, 0.f}
    int nc = tid & 15, pr = tid >> 4;
    const float4* W4 = (const float4*)W;

    for (int t = 0; t < ntap; t++) {
        __syncthreads();
        // stage weights for this tap: 64ci x 16 co4
        {
            const float4* wsrc = W4 + wt[t] * 1024;
#pragma unroll
            for (int j = 0; j < 4; j++) Ws[tid + j * 256] = wsrc[tid + j * 256];
        }
        // stage X tile transposed [ci][px], zero-filled at boundaries
        {
            int sy = yg + dy[t], sx = xg + dx[t];
            bool valid = (sy >= 0) && (sy < h_in) && (sx >= 0) && (sx < w_in);
            const float4* src = (const float4*)(X +
                ((((long)bg << hw_sh) + ((long)sy << w_sh) + sx) << 6)) + half * 8;
#pragma unroll
            for (int j = 0; j < 8; j++) {
                float4 v = valid ? src[j] : make_float4(0.f, 0.f, 0.f, 0.f);
                int k = half * 32 + j * 4;
                Xs[(k + 0) * 128 + mg] = v.x;
                Xs[(k + 1) * 128 + mg] = v.y;
                Xs[(k + 2) * 128 + mg] = v.z;
                Xs[(k + 3) * 128 + mg] = v.w;
            }
        }
        __syncthreads();
        // accumulate: 64 k-steps, 16 packed FFMA2 (=32 MAC) per step per thread
#pragma unroll 8
        for (int k = 0; k < 64; k++) {
            float4 wv = Ws[k * 16 + nc];
            uint64_t wp0, wp1, wp2, wp3;
            asm("mov.b64 %0, {%1, %1};" : "=l"(wp0) : "f"(wv.x));
            asm("mov.b64 %0, {%1, %1};" : "=l"(wp1) : "f"(wv.y));
            asm("mov.b64 %0, {%1, %1};" : "=l"(wp2) : "f"(wv.z));
            asm("mov.b64 %0, {%1, %1};" : "=l"(wp3) : "f"(wv.w));
            const ulonglong2* xr = (const ulonglong2*)&Xs[k * 128 + pr * 8];
            ulonglong2 xa = xr[0];
            ulonglong2 xb = xr[1];
            uint64_t xp[4] = {xa.x, xa.y, xb.x, xb.y};
#pragma unroll
            for (int pp = 0; pp < 4; pp++) {
                asm("fma.rn.f32x2 %0, %1, %2, %0;" : "+l"(acc2[0 + pp])  : "l"(xp[pp]), "l"(wp0));
                asm("fma.rn.f32x2 %0, %1, %2, %0;" : "+l"(acc2[4 + pp])  : "l"(xp[pp]), "l"(wp1));
                asm("fma.rn.f32x2 %0, %1, %2, %0;" : "+l"(acc2[8 + pp])  : "l"(xp[pp]), "l"(wp2));
                asm("fma.rn.f32x2 %0, %1, %2, %0;" : "+l"(acc2[12 + pp]) : "l"(xp[pp]), "l"(wp3));
            }
        }
    }
    // unpack packed accumulators -> av[px][cc]
    float av[8][4];
#pragma unroll
    for (int cc = 0; cc < 4; cc++) {
#pragma unroll
        for (int pp = 0; pp < 4; pp++) {
            float lo, hi;
            asm("mov.b64 {%0, %1}, %2;" : "=f"(lo), "=f"(hi) : "l"(acc2[cc * 4 + pp]));
            av[2 * pp][cc] = lo;
            av[2 * pp + 1][cc] = hi;
        }
    }
    // epilogue: bias + gelu, scatter to interleaved output positions
    float4 bb = __ldg(((const float4*)bias) + nc);
    int h_out = (dim == 0) ? (h_in << 1) : h_in;
    int w_out = (dim == 0) ? w_in : (w_in << 1);
#pragma unroll
    for (int i = 0; i < 8; i++) {
        int q = q0 + pr * 8 + i;
        int b = q >> hw_sh; int rem = q & ((1 << hw_sh) - 1);
        int y = rem >> w_sh; int x = rem & (w_in - 1);
        int oy = (dim == 0) ? (2 * y + parity) : y;
        int ox = (dim == 0) ? x : (2 * x + parity);
        float4 r;
        r.x = gelu_f(av[i][0] + bb.x);
        r.y = gelu_f(av[i][1] + bb.y);
        r.z = gelu_f(av[i][2] + bb.z);
        r.w = gelu_f(av[i][3] + bb.w);
        *((float4*)(Y + ((((long)b * h_out + oy) * w_out + ox) << 6) + nc * 4)) = r;
    }
}

// ------- mask conv(64->4) + softmax + entropy + img pool + masks update + loss -------
__global__ void mask_loss(const float* __restrict__ D, const float* __restrict__ mw,
                          const float* __restrict__ mb, const float* __restrict__ img,
                          const float* __restrict__ masks_in, float* __restrict__ masks_out,
                          int h, int w, int dim, float scale, float* __restrict__ loss) {
    __shared__ float4 ws[576];   // [tap(9)][ci(64)] -> float4 over 4 out channels
    __shared__ float red[256];
    int tid = threadIdx.x;
    const float4* mw4 = (const float4*)mw;
    for (int t = tid; t < 576; t += 256) ws[t] = mw4[t];
    __syncthreads();
    int p = blockIdx.x * 256 + tid;
    int hw = h * w;
    int b = p / hw; int rem = p % hw; int oy = rem / w; int ox = rem % w;
    float4 lg = make_float4(__ldg(mb + 0), __ldg(mb + 1), __ldg(mb + 2), __ldg(mb + 3));
    for (int ky = 0; ky < 3; ky++) {
        int iy = oy + ky - 1; if ((unsigned)iy >= (unsigned)h) continue;
        for (int kx = 0; kx < 3; kx++) {
            int ix = ox + kx - 1; if ((unsigned)ix >= (unsigned)w) continue;
            const float4* xp = (const float4*)(D + ((((long)b * h + iy) * w + ix) << 6));
            const float4* wt = &ws[(ky * 3 + kx) * 64];
#pragma unroll
            for (int q = 0; q < 16; q++) {
                float4 xv = xp[q];
                const float4* wr = wt + q * 4;
                lg.x = fmaf(xv.x, wr[0].x, lg.x); lg.y = fmaf(xv.x, wr[0].y, lg.y);
                lg.z = fmaf(xv.x, wr[0].z, lg.z); lg.w = fmaf(xv.x, wr[0].w, lg.w);
                lg.x = fmaf(xv.y, wr[1].x, lg.x); lg.y = fmaf(xv.y, wr[1].y, lg.y);
                lg.z = fmaf(xv.y, wr[1].z, lg.z); lg.w = fmaf(xv.y, wr[1].w, lg.w);
                lg.x = fmaf(xv.z, wr[2].x, lg.x); lg.y = fmaf(xv.z, wr[2].y, lg.y);
                lg.z = fmaf(xv.z, wr[2].z, lg.z); lg.w = fmaf(xv.z, wr[2].w, lg.w);
                lg.x = fmaf(xv.w, wr[3].x, lg.x); lg.y = fmaf(xv.w, wr[3].y, lg.y);
                lg.z = fmaf(xv.w, wr[3].z, lg.z); lg.w = fmaf(xv.w, wr[3].w, lg.w);
            }
        }
    }
    // softmax over 4
    float m = fmaxf(fmaxf(lg.x, lg.y), fmaxf(lg.z, lg.w));
    float e0 = expf(lg.x - m), e1 = expf(lg.y - m), e2 = expf(lg.z - m), e3 = expf(lg.w - m);
    float inv = 1.0f / (e0 + e1 + e2 + e3);
    float p0 = e0 * inv, p1 = e1 * inv, p2 = e2 * inv, p3 = e3 * inv;
    float sel = p1 + 2.0f * p2 + 3.0f * p3;
    float ent = -(p0 * logf(p0 + 1e-8f) + p1 * logf(p1 + 1e-8f)
                + p2 * logf(p2 + 1e-8f) + p3 * logf(p3 + 1e-8f));
    // average-pooled image at (oy, ox)
    int ph = 256 / h, pw = 256 / w;
    const float* ip = img + (((long)b * 256 + (long)oy * ph) * 256 + (long)ox * pw);
    float s = 0.f;
    for (int a = 0; a < ph; a++)
        for (int c = 0; c < pw; c++) s += ip[a * 256 + c];
    float ids = s / (float)(ph * pw);
    float d = sel * (1.0f / 3.0f) - ids;
    // masks update (repeat along dim, then += 0.25*sel)
    long src;
    if (dim == 0) src = ((long)b * (h >> 1) + (oy >> 1)) * w + ox;
    else          src = ((long)b * h + oy) * (w >> 1) + (ox >> 1);
    masks_out[p] = masks_in[src] + 0.25f * sel;
    // loss reduction: LOSS_W * (mean(entropy) + mean(sqerr))
    red[tid] = ent + d * d;
    __syncthreads();
    for (int off = 128; off > 0; off >>= 1) {
        if (tid < off) red[tid] += red[tid + off];
        __syncthreads();
    }
    if (tid == 0) atomicAdd(loss, red[0] * scale);
}

__global__ void zero_loss_k() { g_loss = 0.0f; }
__global__ void finalize_k(float* out) { out[0] = g_loss; }

static inline int ilog2i(int v) { int s = 0; while ((1 << s) < v) s++; return s; }

// ---------------------------------------------------------------------------
extern "C" void kernel_launch(void* const* d_in, const int* in_sizes, int n_in,
                              void* d_out, int out_size) {
    const float* image  = (const float*)d_in[0];
    // d_in[1] = dynamic_cfg (unused)
    const float* w1 = (const float*)d_in[2];  const float* b1 = (const float*)d_in[3];
    const float* w2 = (const float*)d_in[4];  const float* b2 = (const float*)d_in[5];
    const float* w3 = (const float*)d_in[6];  const float* b3 = (const float*)d_in[7];
    const float* w4 = (const float*)d_in[8];  const float* b4 = (const float*)d_in[9];
    const float* up_w = (const float*)d_in[10]; const float* up_b = (const float*)d_in[11];
    const float* mask_w = (const float*)d_in[12]; const float* mask_b = (const float*)d_in[13];
    const float* masks0 = (const float*)d_in[14];
    float* out = (float*)d_out;

    float *e1, *e2, *e3, *dc0, *dc1, *m0, *m1, *lossp;
    cudaGetSymbolAddress((void**)&e1,  g_enc1);
    cudaGetSymbolAddress((void**)&e2,  g_enc2);
    cudaGetSymbolAddress((void**)&e3,  g_enc3);
    cudaGetSymbolAddress((void**)&dc0, g_dec0);
    cudaGetSymbolAddress((void**)&dc1, g_dec1);
    cudaGetSymbolAddress((void**)&m0,  g_m0);
    cudaGetSymbolAddress((void**)&m1,  g_m1);
    cudaGetSymbolAddress((void**)&lossp, g_loss);

    zero_loss_k<<<1, 1>>>();

    conv1_trio<<<(8 * 256 * 256) / 256, 256>>>(image, w1, b1, e1);
    conv_s2_trio<16, 16, 256, 16><<<(8 * 128 * 128) / 256, 256>>>(e1, w2, b2, e2);
    conv_s2_trio<16, 32, 128, 16><<<(8 * 64 * 64) / 256, 256>>>(e2, w3, b3, e3);
    conv_s2_trio<32, 64, 64, 16><<<(8 * 32 * 32) / 256, 256>>>(e3, w4, b4, dc0);

    const float lws[6] = {0.1f, 0.1f, 0.5f, 0.5f, 1.0f, 1.0f};
    const float* din = dc0;  float* dout_ = dc1;
    const float* min_ = masks0;
    float* mbuf[2] = {m0, m1};
    int h = 32, w = 32;
    for (int i = 0; i < 6; i++) {
        int dim = i % 2;
        int ho = (dim == 0) ? 2 * h : h;
        int wo = (dim == 0) ? w : 2 * w;
        int px = 8 * ho * wo;
        int cls_px = 8 * h * w;                 // pixels per parity class
        int blocks = cls_px / 128;
        int hw_sh = ilog2i(h * w), w_sh = ilog2i(w);
        deconv_gemm<<<blocks, 256>>>(din, dout_, up_w, up_b, h, w, hw_sh, w_sh, dim, 0, 6);
        deconv_gemm<<<blocks, 256>>>(din, dout_, up_w, up_b, h, w, hw_sh, w_sh, dim, 1, 3);
        float* mout = (i == 5) ? (out + 1) : mbuf[i % 2];
        float scale = lws[i] / (float)px;
        mask_loss<<<px / 256, 256>>>(dout_, mask_w, mask_b, image, min_, mout,
                                     ho, wo, dim, scale, lossp);
        min_ = mout;
        const float* t = din; din = dout_; dout_ = (float*)t;
        h = ho; w = wo;
    }
    finalize_k<<<1, 1>>>(out);
}